// round 14
// baseline (speedup 1.0000x reference)
#include <cuda_runtime.h>
#include <cuda_fp16.h>
#include <mma.h>
#include <cstdint>

#define NODES  50000
#define NODESP 50048            // padded rows: unguarded loads/stores on scratch
#define CE     64
#define CN     256
#define KTOT   320
#define COUT   256
#define KSTEP  32
#define NKX    8                // gemm_x: K=256 as 8 chunks
#define STAGES 3
#define NREP   4

#define AS_LD   40
#define BS_LD   264
#define AS_STAGE (64 * AS_LD)
#define BS_STAGE (32 * BS_LD)
#define SMEM_X ((STAGES * AS_STAGE + STAGES * BS_STAGE) * 2)   // 66,048 B

// gemm_a dynamic smem layout (bytes)
#define A2_OFF  0               // 64 x 72 halves = 9216 B
#define B2_OFF  9216            // 64 x 264 halves = 33792 B
#define SMEM_A2 43008           // stg (32x264 fp32 = 33792 B) aliases offset 0

// __device__ scratch (padded)
__device__ float  g_invD[NODESP];
__device__ __half g_Acc[NREP][(size_t)NODESP * CE];
__device__ __half g_Xh[(size_t)NODESP * CN];
__device__ __half g_Bh[KTOT * COUT];
__device__ float  g_tmp[(size_t)NODESP * COUT];     // X@Ws + bias (fp32)

// ---------------------------------------------------------------------------
__device__ __forceinline__ void cp_async16(void* smem, const void* gsrc) {
    uint32_t s = (uint32_t)__cvta_generic_to_shared(smem);
    asm volatile("cp.async.cg.shared.global [%0], [%1], 16;\n"
                 :: "r"(s), "l"(gsrc));
}
#define CP_COMMIT() asm volatile("cp.async.commit_group;\n" ::: "memory")
#define CP_WAIT(n)  asm volatile("cp.async.wait_group %0;\n" :: "n"(n) : "memory")

// ---------------------------------------------------------------------------
// zero replicas (padded) + invD (0 in slack rows)
// ---------------------------------------------------------------------------
__global__ void zero_kernel(const float* __restrict__ D) {
    int i = blockIdx.x * blockDim.x + threadIdx.x;
    if (i < NODESP) g_invD[i] = (i < NODES) ? __frcp_rn(__ldg(D + i)) : 0.f;
    const int tot = NREP * NODESP * 8;   // uint4 chunks
    if (i < tot)
        reinterpret_cast<uint4*>(g_Acc)[i] = make_uint4(0u, 0u, 0u, 0u);
}

__global__ void wtrans_kernel(const float* __restrict__ Wp,
                              const float* __restrict__ Ws) {
    int idx = blockIdx.x * 256 + threadIdx.x;
    if (idx >= KTOT * COUT) return;
    int k = idx >> 8, n = idx & 255;
    float v = (k < 64) ? __ldg(Wp + k * COUT + n)
                       : __ldg(Ws + (size_t)(k - 64) * COUT + n);
    g_Bh[idx] = __float2half_rn(v);
}

__global__ void convx_kernel(const float* __restrict__ X) {
    int i = blockIdx.x * blockDim.x + threadIdx.x;
    const int tot = NODES * CN / 2;
    if (i >= tot) return;
    float2 v = *reinterpret_cast<const float2*>(X + (size_t)i * 2);
    *reinterpret_cast<__half2*>(g_Xh + (size_t)i * 2) =
        __floats2half2_rn(v.x, v.y);
}

// ---------------------------------------------------------------------------
// scatter: 8 threads/edge, unscaled fp16x2 red into replica e&3
// ---------------------------------------------------------------------------
__global__ void scatter_kernel(const float4* __restrict__ ea,
                               const int* __restrict__ row_idx, int total8) {
    int i = blockIdx.x * 256 + threadIdx.x;
    if (i >= total8) return;
    int e = i >> 3, t = i & 7;
    int r = __ldg(row_idx + e);
    float4 v0 = __ldg(ea + (size_t)e * 16 + t * 2);
    float4 v1 = __ldg(ea + (size_t)e * 16 + t * 2 + 1);
    __half2 h0 = __floats2half2_rn(v0.x, v0.y);
    __half2 h1 = __floats2half2_rn(v0.z, v0.w);
    __half2 h2 = __floats2half2_rn(v1.x, v1.y);
    __half2 h3 = __floats2half2_rn(v1.z, v1.w);
    __half* dst = g_Acc[e & 3] + (size_t)r * CE + t * 8;
    asm volatile("red.global.add.noftz.v4.f16x2 [%0], {%1, %2, %3, %4};"
                 :: "l"(dst),
                    "r"(*reinterpret_cast<uint32_t*>(&h0)),
                    "r"(*reinterpret_cast<uint32_t*>(&h1)),
                    "r"(*reinterpret_cast<uint32_t*>(&h2)),
                    "r"(*reinterpret_cast<uint32_t*>(&h3))
                 : "memory");
}

// ---------------------------------------------------------------------------
// gemm_x: tmp = X @ Ws + bias   (K=256; overlaps with scatter)
//   CTA 64x256, 256 thr, 2 CTA/SM, 3-stage cp.async, unguarded (padded bufs)
// ---------------------------------------------------------------------------
using namespace nvcuda;
typedef wmma::fragment<wmma::matrix_a, 16, 16, 16, __half, wmma::row_major> AFrag;
typedef wmma::fragment<wmma::matrix_b, 16, 16, 16, __half, wmma::row_major> BFrag;

__device__ __forceinline__ void ldB_x(__half* Bs, int ks, int tid) {
    const __half* bsrc = g_Bh + (size_t)(64 + ks * 32) * COUT;
#pragma unroll
    for (int i = 0; i < 4; i++) {
        int j = tid + i * 256;
        int r = j >> 5, c8 = (j & 31) * 8;
        cp_async16(Bs + r * BS_LD + c8, bsrc + r * COUT + c8);
    }
}
__device__ __forceinline__ void ldA_x(__half* As, int ks, int row0, int tid) {
    int r = tid >> 2, c8 = (tid & 3) * 8;
    cp_async16(As + r * AS_LD + c8,
               g_Xh + (size_t)(row0 + r) * CN + ks * 32 + c8);
}

__global__ __launch_bounds__(256, 2)
void gemm_x_kernel(const float* __restrict__ bp, const float* __restrict__ bs) {
    extern __shared__ __half smem[];
    __half* AsBase = smem;
    __half* BsBase = smem + STAGES * AS_STAGE;

    const int tid  = threadIdx.x;
    const int warp = tid >> 5;
    const int wm   = warp >> 2;
    const int wn   = warp & 3;
    const int row0 = blockIdx.x * 64;

    float* biasf = reinterpret_cast<float*>(smem);   // 16 x 264 fp32
    for (int i = tid; i < 16 * 256; i += 256) {
        int r = i >> 8, c = i & 255;
        biasf[r * 264 + c] = __ldg(bp + c) + __ldg(bs + c);
    }
    __syncthreads();

    wmma::fragment<wmma::accumulator, 16, 16, 16, float> acc[2][4];
#pragma unroll
    for (int mi = 0; mi < 2; mi++)
#pragma unroll
        for (int ni = 0; ni < 4; ni++)
            wmma::load_matrix_sync(acc[mi][ni], biasf + wn * 64 + ni * 16,
                                   264, wmma::mem_row_major);
    __syncthreads();

    ldA_x(AsBase + 0 * AS_STAGE, 0, row0, tid);
    ldB_x(BsBase + 0 * BS_STAGE, 0, tid);
    CP_COMMIT();
    ldA_x(AsBase + 1 * AS_STAGE, 1, row0, tid);
    ldB_x(BsBase + 1 * BS_STAGE, 1, tid);
    CP_COMMIT();

    for (int ks = 0; ks < NKX; ks++) {
        const int cbuf = ks % STAGES;
        const __half* As = AsBase + cbuf * AS_STAGE;
        const __half* Bs = BsBase + cbuf * BS_STAGE;

        if (ks < NKX - 1) { CP_WAIT(1); } else { CP_WAIT(0); }
        __syncthreads();

        if (ks + 2 < NKX) {
            const int wbuf = (ks + 2) % STAGES;
            ldA_x(AsBase + wbuf * AS_STAGE, ks + 2, row0, tid);
            ldB_x(BsBase + wbuf * BS_STAGE, ks + 2, tid);
            CP_COMMIT();
        }

#pragma unroll
        for (int k16 = 0; k16 < 2; k16++) {
            AFrag af[2];
            BFrag bf[4];
#pragma unroll
            for (int mi = 0; mi < 2; mi++)
                wmma::load_matrix_sync(af[mi],
                    As + (wm * 32 + mi * 16) * AS_LD + k16 * 16, AS_LD);
#pragma unroll
            for (int ni = 0; ni < 4; ni++)
                wmma::load_matrix_sync(bf[ni],
                    Bs + (k16 * 16) * BS_LD + wn * 64 + ni * 16, BS_LD);
#pragma unroll
            for (int mi = 0; mi < 2; mi++)
#pragma unroll
                for (int ni = 0; ni < 4; ni++)
                    wmma::mma_sync(acc[mi][ni], af[mi], bf[ni], acc[mi][ni]);
        }
    }

    // unguarded fp32 store into padded g_tmp (no relu here)
#pragma unroll
    for (int mi = 0; mi < 2; mi++)
#pragma unroll
        for (int ni = 0; ni < 4; ni++)
            wmma::store_matrix_sync(
                g_tmp + (size_t)(row0 + wm * 32 + mi * 16) * COUT
                      + wn * 64 + ni * 16,
                acc[mi][ni], COUT, wmma::mem_row_major);
}

// ---------------------------------------------------------------------------
// gemm_a: out = relu(tmp + (sum(reps)*invD) @ Wp)   (K=64, single shot)
// ---------------------------------------------------------------------------
__global__ __launch_bounds__(256, 2)
void gemm_a_kernel(float* __restrict__ out, int nNodes) {
    extern __shared__ __half smem[];
    __half* Asm = smem + A2_OFF / 2;           // 64 x 72 halves
    __half* Bsm = smem + B2_OFF / 2;           // 64 x 264 halves
    float*  stg = reinterpret_cast<float*>(smem);   // 32 x 264 fp32 (aliases)

    const int tid  = threadIdx.x;
    const int warp = tid >> 5;
    const int wm   = warp >> 2;
    const int wn   = warp & 3;
    const int row0 = blockIdx.x * 64;

    // B: k rows 0..63 of g_Bh (Wp part), 8 x 16B per thread
#pragma unroll
    for (int i = 0; i < 8; i++) {
        int j = tid + i * 256;
        int r = j >> 5, c8 = (j & 31) * 8;
        cp_async16(Bsm + r * BS_LD + c8, g_Bh + (size_t)r * COUT + c8);
    }
    CP_COMMIT();

    // A: 64 rows x 64 halves from replica sum * invD (2 uint4 per thread)
#pragma unroll
    for (int i = 0; i < 2; i++) {
        int j = tid + i * 256;
        int r = j >> 3, c8 = j & 7;
        int gr = row0 + r;
        float acc8[8] = {0.f, 0.f, 0.f, 0.f, 0.f, 0.f, 0.f, 0.f};
#pragma unroll
        for (int rep = 0; rep < NREP; rep++) {
            uint4 u = *reinterpret_cast<const uint4*>(
                g_Acc[rep] + (size_t)gr * CE + c8 * 8);
            const __half2* h = reinterpret_cast<const __half2*>(&u);
#pragma unroll
            for (int q = 0; q < 4; q++) {
                float2 f = __half22float2(h[q]);
                acc8[q * 2]     += f.x;
                acc8[q * 2 + 1] += f.y;
            }
        }
        float sc = g_invD[gr];
        __half2 o[4];
#pragma unroll
        for (int q = 0; q < 4; q++)
            o[q] = __floats2half2_rn(acc8[q * 2] * sc, acc8[q * 2 + 1] * sc);
        *reinterpret_cast<uint4*>(Asm + r * 72 + c8 * 8) =
            *reinterpret_cast<uint4*>(o);
    }

    CP_WAIT(0);
    __syncthreads();

    wmma::fragment<wmma::accumulator, 16, 16, 16, float> acc[2][4];
#pragma unroll
    for (int mi = 0; mi < 2; mi++)
#pragma unroll
        for (int ni = 0; ni < 4; ni++)
            wmma::fill_fragment(acc[mi][ni], 0.f);

#pragma unroll
    for (int k16 = 0; k16 < 4; k16++) {
        AFrag af[2];
        BFrag bf[4];
#pragma unroll
        for (int mi = 0; mi < 2; mi++)
            wmma::load_matrix_sync(af[mi],
                Asm + (wm * 32 + mi * 16) * 72 + k16 * 16, 72);
#pragma unroll
        for (int ni = 0; ni < 4; ni++)
            wmma::load_matrix_sync(bf[ni],
                Bsm + (k16 * 16) * BS_LD + wn * 64 + ni * 16, BS_LD);
#pragma unroll
        for (int mi = 0; mi < 2; mi++)
#pragma unroll
            for (int ni = 0; ni < 4; ni++)
                wmma::mma_sync(acc[mi][ni], af[mi], bf[ni], acc[mi][ni]);
    }

    // epilogue: +tmp, relu, guarded store (stg aliases A/B smem)
    for (int chunk = 0; chunk < 2; chunk++) {
        __syncthreads();
        if (wm == chunk) {
#pragma unroll
            for (int mi = 0; mi < 2; mi++)
#pragma unroll
                for (int ni = 0; ni < 4; ni++)
                    wmma::store_matrix_sync(
                        stg + (mi * 16) * 264 + wn * 64 + ni * 16,
                        acc[mi][ni], 264, wmma::mem_row_major);
        }
        __syncthreads();
        int base = row0 + chunk * 32;
        for (int idx = tid; idx < 32 * 256; idx += 256) {
            int r = idx >> 8, c = idx & 255;
            int gr = base + r;
            if (gr < nNodes) {
                float v = stg[r * 264 + c] + g_tmp[(size_t)gr * COUT + c];
                out[(size_t)gr * COUT + c] = fmaxf(v, 0.f);
            }
        }
    }
}

// ---------------------------------------------------------------------------
extern "C" void kernel_launch(void* const* d_in, const int* in_sizes, int n_in,
                              void* d_out, int out_size) {
    const float*  D   = (const float*)d_in[0];
    const int*    row = (const int*)d_in[1];
    const float4* ea  = (const float4*)d_in[2];
    const float*  X   = (const float*)d_in[3];
    const float*  Wp  = (const float*)d_in[4];
    const float*  bp  = (const float*)d_in[5];
    const float*  Ws  = (const float*)d_in[6];
    const float*  bs  = (const float*)d_in[7];
    float* out = (float*)d_out;

    const int nNodes = in_sizes[0];
    const int E      = in_sizes[1];

    static cudaStream_t s2;
    static cudaEvent_t evFork, evX;
    static bool init = false;
    if (!init) {
        cudaStreamCreateWithFlags(&s2, cudaStreamNonBlocking);
        cudaEventCreateWithFlags(&evFork, cudaEventDisableTiming);
        cudaEventCreateWithFlags(&evX, cudaEventDisableTiming);
        cudaFuncSetAttribute(gemm_x_kernel,
                             cudaFuncAttributeMaxDynamicSharedMemorySize,
                             SMEM_X);
        init = true;
    }

    // fork side stream off the (possibly capturing) main stream
    cudaEventRecord(evFork, 0);
    cudaStreamWaitEvent(s2, evFork, 0);

    // s2: weights/X conversion + X-GEMM (independent of scatter)
    {
        int n = KTOT * COUT;
        wtrans_kernel<<<(n + 255) / 256, 256, 0, s2>>>(Wp, Ws);
    }
    {
        int n = NODES * CN / 2;
        convx_kernel<<<(n + 255) / 256, 256, 0, s2>>>(X);
    }
    {
        int grid = (NODES + 63) / 64;   // 782, covers padded rows unguarded
        gemm_x_kernel<<<grid, 256, SMEM_X, s2>>>(bp, bs);
    }
    cudaEventRecord(evX, s2);

    // main stream: zero + scatter (DRAM-bound; overlaps with s2)
    {
        int n = NREP * NODESP * 8;
        zero_kernel<<<(n + 255) / 256, 256>>>(D);
    }
    {
        int total8 = E * 8;
        scatter_kernel<<<(total8 + 255) / 256, 256>>>(ea, row, total8);
    }

    // join, then final K=64 GEMM + epilogue
    cudaStreamWaitEvent(0, evX, 0);
    {
        int grid = (NODES + 63) / 64;
        gemm_a_kernel<<<grid, 256, SMEM_A2>>>(out, nNodes);
    }
}

// round 15
// speedup vs baseline: 1.7679x; 1.7679x over previous
#include <cuda_runtime.h>
#include <cuda_fp16.h>
#include <mma.h>
#include <cstdint>

#define NODES  50000
#define NODESP 50048
#define CE     64
#define CN     256
#define KTOT   320
#define COUT   256
#define KSTEP  32
#define NKS    10
#define STAGES 3
#define NREP   4

#define AS_LD   40
#define BS_LD   264
#define AS_STAGE (64 * AS_LD)
#define BS_STAGE (32 * BS_LD)
#define SMEM_BYTES ((STAGES * AS_STAGE + STAGES * BS_STAGE) * 2)  // 66,048 B

// __device__ scratch (padded rows)
__device__ float  g_invD[NODESP];
__device__ __half g_Acc[NREP][(size_t)NODESP * CE];
__device__ __half g_Xh[(size_t)NODESP * CN];
__device__ __half g_Bh[KTOT * COUT];

// init domain sizes
#define N_CONVX (NODES * CN / 2)            // 6,400,000 half2
#define N_ZERO  (NREP * NODESP * 8)         // 1,601,536 uint4
#define N_INVD  (NODESP)
#define N_WT    (KTOT * COUT)
#define N_INIT  (N_CONVX + N_ZERO + N_INVD + N_WT)

// ---------------------------------------------------------------------------
__device__ __forceinline__ void cp_async16(void* smem, const void* gsrc) {
    uint32_t s = (uint32_t)__cvta_generic_to_shared(smem);
    asm volatile("cp.async.cg.shared.global [%0], [%1], 16;\n"
                 :: "r"(s), "l"(gsrc));
}
#define CP_COMMIT() asm volatile("cp.async.commit_group;\n" ::: "memory")
#define CP_WAIT(n)  asm volatile("cp.async.wait_group %0;\n" :: "n"(n) : "memory")

// ---------------------------------------------------------------------------
// 1) fused init: convx | zero replicas | invD | wtrans
// ---------------------------------------------------------------------------
__global__ void init_kernel(const float* __restrict__ D,
                            const float* __restrict__ X,
                            const float* __restrict__ Wp,
                            const float* __restrict__ Ws) {
    int i = blockIdx.x * blockDim.x + threadIdx.x;
    if (i < N_CONVX) {
        float2 v = *reinterpret_cast<const float2*>(X + (size_t)i * 2);
        *reinterpret_cast<__half2*>(g_Xh + (size_t)i * 2) =
            __floats2half2_rn(v.x, v.y);
        return;
    }
    i -= N_CONVX;
    if (i < N_ZERO) {
        reinterpret_cast<uint4*>(g_Acc)[i] = make_uint4(0u, 0u, 0u, 0u);
        return;
    }
    i -= N_ZERO;
    if (i < N_INVD) {
        g_invD[i] = (i < NODES) ? __frcp_rn(__ldg(D + i)) : 0.f;
        return;
    }
    i -= N_INVD;
    if (i < N_WT) {
        int k = i >> 8, n = i & 255;
        float v = (k < 64) ? __ldg(Wp + k * COUT + n)
                           : __ldg(Ws + (size_t)(k - 64) * COUT + n);
        g_Bh[i] = __float2half_rn(v);
    }
}

// ---------------------------------------------------------------------------
// 2) scatter: 8 threads/edge, streaming edge loads (__ldcs), fp16x2 red into
//    replica e&3
// ---------------------------------------------------------------------------
__global__ void scatter_kernel(const float4* __restrict__ ea,
                               const int* __restrict__ row_idx, int total8) {
    int i = blockIdx.x * 256 + threadIdx.x;
    if (i >= total8) return;
    int e = i >> 3, t = i & 7;
    int r = __ldg(row_idx + e);
    float4 v0 = __ldcs(ea + (size_t)e * 16 + t * 2);
    float4 v1 = __ldcs(ea + (size_t)e * 16 + t * 2 + 1);
    __half2 h0 = __floats2half2_rn(v0.x, v0.y);
    __half2 h1 = __floats2half2_rn(v0.z, v0.w);
    __half2 h2 = __floats2half2_rn(v1.x, v1.y);
    __half2 h3 = __floats2half2_rn(v1.z, v1.w);
    __half* dst = g_Acc[e & 3] + (size_t)r * CE + t * 8;
    asm volatile("red.global.add.noftz.v4.f16x2 [%0], {%1, %2, %3, %4};"
                 :: "l"(dst),
                    "r"(*reinterpret_cast<uint32_t*>(&h0)),
                    "r"(*reinterpret_cast<uint32_t*>(&h1)),
                    "r"(*reinterpret_cast<uint32_t*>(&h2)),
                    "r"(*reinterpret_cast<uint32_t*>(&h3))
                 : "memory");
}

// ---------------------------------------------------------------------------
// 3) fp16 GEMM  out = relu([sum(reps)/D | X] @ Bh + bias)   (R13, verbatim)
// ---------------------------------------------------------------------------
using namespace nvcuda;
typedef wmma::fragment<wmma::matrix_a, 16, 16, 16, __half, wmma::row_major> AFrag;
typedef wmma::fragment<wmma::matrix_b, 16, 16, 16, __half, wmma::row_major> BFrag;

__device__ __forceinline__ void load_B(__half* Bs, int ks, int tid) {
    const __half* bsrc = g_Bh + (size_t)ks * 32 * COUT;
#pragma unroll
    for (int i = 0; i < 4; i++) {
        int j = tid + i * 256;
        int r = j >> 5, c8 = (j & 31) * 8;
        cp_async16(Bs + r * BS_LD + c8, bsrc + r * COUT + c8);
    }
}

__device__ __forceinline__ void load_A_x(__half* As, int ks, int row0,
                                         int nNodes, int tid) {
    const int k0 = ks * KSTEP - 64;
    int r  = tid >> 2, c8 = (tid & 3) * 8;
    int gr = row0 + r;
    int grc = (gr < nNodes) ? gr : (NODES - 1);   // padded-safe clamp
    cp_async16(As + r * AS_LD + c8, g_Xh + (size_t)grc * CN + k0 + c8);
}

__device__ __forceinline__ void build_A_rep(__half* As, int s, int row0,
                                            int nNodes, int tid) {
    int r  = tid >> 2, c8 = (tid & 3) * 8;
    int gr = row0 + r;
    __half2 o[4] = {__half2{}, __half2{}, __half2{}, __half2{}};
    if (gr < nNodes) {
        float acc[8] = {0.f, 0.f, 0.f, 0.f, 0.f, 0.f, 0.f, 0.f};
#pragma unroll
        for (int rep = 0; rep < NREP; rep++) {
            uint4 u = *reinterpret_cast<const uint4*>(
                g_Acc[rep] + (size_t)gr * CE + s * 32 + c8);
            const __half2* h = reinterpret_cast<const __half2*>(&u);
#pragma unroll
            for (int j = 0; j < 4; j++) {
                float2 f = __half22float2(h[j]);
                acc[j * 2]     += f.x;
                acc[j * 2 + 1] += f.y;
            }
        }
        float sc = __ldg(g_invD + gr);
#pragma unroll
        for (int j = 0; j < 4; j++)
            o[j] = __floats2half2_rn(acc[j * 2] * sc, acc[j * 2 + 1] * sc);
    }
    *reinterpret_cast<uint4*>(As + r * AS_LD + c8) =
        *reinterpret_cast<uint4*>(o);
}

__global__ __launch_bounds__(256, 2)
void gemm_kernel(const float* __restrict__ bp, const float* __restrict__ bs,
                 float* __restrict__ out, int nNodes) {
    extern __shared__ __half smem[];
    __half* AsBase = smem;
    __half* BsBase = smem + STAGES * AS_STAGE;

    const int tid  = threadIdx.x;
    const int warp = tid >> 5;
    const int wm   = warp >> 2;
    const int wn   = warp & 3;
    const int row0 = blockIdx.x * 64;

    float* biasf = reinterpret_cast<float*>(smem);
    for (int i = tid; i < 16 * 256; i += 256) {
        int r = i >> 8, c = i & 255;
        biasf[r * 264 + c] = __ldg(bp + c) + __ldg(bs + c);
    }
    __syncthreads();

    wmma::fragment<wmma::accumulator, 16, 16, 16, float> acc[2][4];
#pragma unroll
    for (int mi = 0; mi < 2; mi++)
#pragma unroll
        for (int ni = 0; ni < 4; ni++)
            wmma::load_matrix_sync(acc[mi][ni], biasf + wn * 64 + ni * 16,
                                   264, wmma::mem_row_major);
    __syncthreads();

    build_A_rep(AsBase + 0 * AS_STAGE, 0, row0, nNodes, tid);
    load_B(BsBase + 0 * BS_STAGE, 0, tid);
    CP_COMMIT();
    build_A_rep(AsBase + 1 * AS_STAGE, 1, row0, nNodes, tid);
    load_B(BsBase + 1 * BS_STAGE, 1, tid);
    CP_COMMIT();

    for (int ks = 0; ks < NKS; ks++) {
        const int cbuf = ks % STAGES;
        const __half* As = AsBase + cbuf * AS_STAGE;
        const __half* Bs = BsBase + cbuf * BS_STAGE;

        if (ks < NKS - 1) { CP_WAIT(1); } else { CP_WAIT(0); }
        __syncthreads();

        if (ks + 2 < NKS) {
            const int wbuf = (ks + 2) % STAGES;
            load_A_x(AsBase + wbuf * AS_STAGE, ks + 2, row0, nNodes, tid);
            load_B(BsBase + wbuf * BS_STAGE, ks + 2, tid);
            CP_COMMIT();
        }

#pragma unroll
        for (int k16 = 0; k16 < 2; k16++) {
            AFrag af[2];
            BFrag bf[4];
#pragma unroll
            for (int mi = 0; mi < 2; mi++)
                wmma::load_matrix_sync(af[mi],
                    As + (wm * 32 + mi * 16) * AS_LD + k16 * 16, AS_LD);
#pragma unroll
            for (int ni = 0; ni < 4; ni++)
                wmma::load_matrix_sync(bf[ni],
                    Bs + (k16 * 16) * BS_LD + wn * 64 + ni * 16, BS_LD);
#pragma unroll
            for (int mi = 0; mi < 2; mi++)
#pragma unroll
                for (int ni = 0; ni < 4; ni++)
                    wmma::mma_sync(acc[mi][ni], af[mi], bf[ni], acc[mi][ni]);
        }
    }

#pragma unroll
    for (int mi = 0; mi < 2; mi++)
#pragma unroll
        for (int ni = 0; ni < 4; ni++)
#pragma unroll
            for (int t = 0; t < acc[mi][ni].num_elements; t++)
                acc[mi][ni].x[t] = fmaxf(acc[mi][ni].x[t], 0.f);

    __syncthreads();

    if (row0 + 64 <= nNodes) {
#pragma unroll
        for (int mi = 0; mi < 2; mi++)
#pragma unroll
            for (int ni = 0; ni < 4; ni++)
                wmma::store_matrix_sync(
                    out + (size_t)(row0 + wm * 32 + mi * 16) * COUT
                        + wn * 64 + ni * 16,
                    acc[mi][ni], COUT, wmma::mem_row_major);
    } else {
        float* stg = reinterpret_cast<float*>(smem);
        for (int chunk = 0; chunk < 2; chunk++) {
            __syncthreads();
            if (wm == chunk) {
#pragma unroll
                for (int mi = 0; mi < 2; mi++)
#pragma unroll
                    for (int ni = 0; ni < 4; ni++)
                        wmma::store_matrix_sync(
                            stg + (mi * 16) * 264 + wn * 64 + ni * 16,
                            acc[mi][ni], 264, wmma::mem_row_major);
            }
            __syncthreads();
            int base = row0 + chunk * 32;
            for (int idx = tid; idx < 32 * 256; idx += 256) {
                int r = idx >> 8, c = idx & 255;
                int gr = base + r;
                if (gr < nNodes)
                    out[(size_t)gr * COUT + c] = stg[r * 264 + c];
            }
        }
    }
}

// ---------------------------------------------------------------------------
extern "C" void kernel_launch(void* const* d_in, const int* in_sizes, int n_in,
                              void* d_out, int out_size) {
    const float*  D   = (const float*)d_in[0];
    const int*    row = (const int*)d_in[1];
    const float4* ea  = (const float4*)d_in[2];
    const float*  X   = (const float*)d_in[3];
    const float*  Wp  = (const float*)d_in[4];
    const float*  bp  = (const float*)d_in[5];
    const float*  Ws  = (const float*)d_in[6];
    const float*  bs  = (const float*)d_in[7];
    float* out = (float*)d_out;

    const int nNodes = in_sizes[0];
    const int E      = in_sizes[1];

    static bool attr_set = false;
    if (!attr_set) {
        cudaFuncSetAttribute(gemm_kernel,
                             cudaFuncAttributeMaxDynamicSharedMemorySize,
                             SMEM_BYTES);
        attr_set = true;
    }

    {   // fused init: convx + zero replicas + invD + wtrans
        init_kernel<<<(N_INIT + 255) / 256, 256>>>(D, X, Wp, Ws);
    }
    {   // scatter
        int total8 = E * 8;
        scatter_kernel<<<(total8 + 255) / 256, 256>>>(ea, row, total8);
    }
    {   // fp16 GEMM (merge folded into prologue)
        int grid = (nNodes + 63) / 64;
        gemm_kernel<<<grid, 256, SMEM_BYTES>>>(bp, bs, out, nNodes);
    }
}

// round 16
// speedup vs baseline: 1.8641x; 1.0544x over previous
#include <cuda_runtime.h>
#include <cuda_fp16.h>
#include <mma.h>
#include <cstdint>

#define NODES  50000
#define NODESP 50048
#define CE     64
#define CN     256
#define KTOT   320
#define COUT   256
#define KSTEP  32
#define NKS    10
#define STAGES 3
#define NREP   4

#define AS_LD   40
#define BS_LD   264
#define AS_STAGE (64 * AS_LD)
#define BS_STAGE (32 * BS_LD)
#define SMEM_BYTES ((STAGES * AS_STAGE + STAGES * BS_STAGE) * 2)  // 66,048 B

// __device__ scratch (padded rows)
__device__ float  g_invD[NODESP];
__device__ __half g_Acc[NREP][(size_t)NODESP * CE];
__device__ __half g_Xh[(size_t)NODESP * CN];
__device__ __half g_Bh[KTOT * COUT];

// init domains (vectorized)
#define N_CONVX (NODES * CN / 8)             // 1,600,000: 8 floats -> 8 halves
#define N_ZERO  (NREP * NODESP * 4)          // 800,768: 2 x uint4 per thread
#define N_INVD  (NODESP)
#define N_WT    (KTOT * COUT)
#define N_INIT  (N_CONVX + N_ZERO + N_INVD + N_WT)

// ---------------------------------------------------------------------------
__device__ __forceinline__ void cp_async16(void* smem, const void* gsrc) {
    uint32_t s = (uint32_t)__cvta_generic_to_shared(smem);
    asm volatile("cp.async.cg.shared.global [%0], [%1], 16;\n"
                 :: "r"(s), "l"(gsrc));
}
#define CP_COMMIT() asm volatile("cp.async.commit_group;\n" ::: "memory")
#define CP_WAIT(n)  asm volatile("cp.async.wait_group %0;\n" :: "n"(n) : "memory")

// ---------------------------------------------------------------------------
// 1) fused init (vectorized): convx | zero replicas | invD | wtrans
// ---------------------------------------------------------------------------
__global__ void init_kernel(const float* __restrict__ D,
                            const float* __restrict__ X,
                            const float* __restrict__ Wp,
                            const float* __restrict__ Ws) {
    int i = blockIdx.x * blockDim.x + threadIdx.x;
    if (i < N_CONVX) {
        // 8 fp32 -> 8 half (32B read, 16B write)
        const float4* src = reinterpret_cast<const float4*>(X) + (size_t)i * 2;
        float4 a = __ldcs(src);
        float4 b = __ldcs(src + 1);
        __half2 o[4] = { __floats2half2_rn(a.x, a.y),
                         __floats2half2_rn(a.z, a.w),
                         __floats2half2_rn(b.x, b.y),
                         __floats2half2_rn(b.z, b.w) };
        *(reinterpret_cast<uint4*>(g_Xh) + i) = *reinterpret_cast<uint4*>(o);
        return;
    }
    i -= N_CONVX;
    if (i < N_ZERO) {
        uint4 z = make_uint4(0u, 0u, 0u, 0u);
        uint4* p = reinterpret_cast<uint4*>(g_Acc) + (size_t)i * 2;
        p[0] = z;
        p[1] = z;
        return;
    }
    i -= N_ZERO;
    if (i < N_INVD) {
        g_invD[i] = (i < NODES) ? __frcp_rn(__ldg(D + i)) : 0.f;
        return;
    }
    i -= N_INVD;
    if (i < N_WT) {
        int k = i >> 8, n = i & 255;
        float v = (k < 64) ? __ldg(Wp + k * COUT + n)
                           : __ldg(Ws + (size_t)(k - 64) * COUT + n);
        g_Bh[i] = __float2half_rn(v);
    }
}

// ---------------------------------------------------------------------------
// 2) scatter: 8 threads/edge, streaming edge loads, fp16x2 red into replica
//    (R15 verbatim)
// ---------------------------------------------------------------------------
__global__ void scatter_kernel(const float4* __restrict__ ea,
                               const int* __restrict__ row_idx, int total8) {
    int i = blockIdx.x * 256 + threadIdx.x;
    if (i >= total8) return;
    int e = i >> 3, t = i & 7;
    int r = __ldg(row_idx + e);
    float4 v0 = __ldcs(ea + (size_t)e * 16 + t * 2);
    float4 v1 = __ldcs(ea + (size_t)e * 16 + t * 2 + 1);
    __half2 h0 = __floats2half2_rn(v0.x, v0.y);
    __half2 h1 = __floats2half2_rn(v0.z, v0.w);
    __half2 h2 = __floats2half2_rn(v1.x, v1.y);
    __half2 h3 = __floats2half2_rn(v1.z, v1.w);
    __half* dst = g_Acc[e & 3] + (size_t)r * CE + t * 8;
    asm volatile("red.global.add.noftz.v4.f16x2 [%0], {%1, %2, %3, %4};"
                 :: "l"(dst),
                    "r"(*reinterpret_cast<uint32_t*>(&h0)),
                    "r"(*reinterpret_cast<uint32_t*>(&h1)),
                    "r"(*reinterpret_cast<uint32_t*>(&h2)),
                    "r"(*reinterpret_cast<uint32_t*>(&h3))
                 : "memory");
}

// ---------------------------------------------------------------------------
// 3) fp16 GEMM  out = relu([sum(reps)/D | X] @ Bh + bias)   (R15 verbatim)
// ---------------------------------------------------------------------------
using namespace nvcuda;
typedef wmma::fragment<wmma::matrix_a, 16, 16, 16, __half, wmma::row_major> AFrag;
typedef wmma::fragment<wmma::matrix_b, 16, 16, 16, __half, wmma::row_major> BFrag;

__device__ __forceinline__ void load_B(__half* Bs, int ks, int tid) {
    const __half* bsrc = g_Bh + (size_t)ks * 32 * COUT;
#pragma unroll
    for (int i = 0; i < 4; i++) {
        int j = tid + i * 256;
        int r = j >> 5, c8 = (j & 31) * 8;
        cp_async16(Bs + r * BS_LD + c8, bsrc + r * COUT + c8);
    }
}

__device__ __forceinline__ void load_A_x(__half* As, int ks, int row0,
                                         int nNodes, int tid) {
    const int k0 = ks * KSTEP - 64;
    int r  = tid >> 2, c8 = (tid & 3) * 8;
    int gr = row0 + r;
    int grc = (gr < nNodes) ? gr : (NODES - 1);
    cp_async16(As + r * AS_LD + c8, g_Xh + (size_t)grc * CN + k0 + c8);
}

__device__ __forceinline__ void build_A_rep(__half* As, int s, int row0,
                                            int nNodes, int tid) {
    int r  = tid >> 2, c8 = (tid & 3) * 8;
    int gr = row0 + r;
    __half2 o[4] = {__half2{}, __half2{}, __half2{}, __half2{}};
    if (gr < nNodes) {
        float acc[8] = {0.f, 0.f, 0.f, 0.f, 0.f, 0.f, 0.f, 0.f};
#pragma unroll
        for (int rep = 0; rep < NREP; rep++) {
            uint4 u = *reinterpret_cast<const uint4*>(
                g_Acc[rep] + (size_t)gr * CE + s * 32 + c8);
            const __half2* h = reinterpret_cast<const __half2*>(&u);
#pragma unroll
            for (int j = 0; j < 4; j++) {
                float2 f = __half22float2(h[j]);
                acc[j * 2]     += f.x;
                acc[j * 2 + 1] += f.y;
            }
        }
        float sc = __ldg(g_invD + gr);
#pragma unroll
        for (int j = 0; j < 4; j++)
            o[j] = __floats2half2_rn(acc[j * 2] * sc, acc[j * 2 + 1] * sc);
    }
    *reinterpret_cast<uint4*>(As + r * AS_LD + c8) =
        *reinterpret_cast<uint4*>(o);
}

__global__ __launch_bounds__(256, 2)
void gemm_kernel(const float* __restrict__ bp, const float* __restrict__ bs,
                 float* __restrict__ out, int nNodes) {
    extern __shared__ __half smem[];
    __half* AsBase = smem;
    __half* BsBase = smem + STAGES * AS_STAGE;

    const int tid  = threadIdx.x;
    const int warp = tid >> 5;
    const int wm   = warp >> 2;
    const int wn   = warp & 3;
    const int row0 = blockIdx.x * 64;

    float* biasf = reinterpret_cast<float*>(smem);
    for (int i = tid; i < 16 * 256; i += 256) {
        int r = i >> 8, c = i & 255;
        biasf[r * 264 + c] = __ldg(bp + c) + __ldg(bs + c);
    }
    __syncthreads();

    wmma::fragment<wmma::accumulator, 16, 16, 16, float> acc[2][4];
#pragma unroll
    for (int mi = 0; mi < 2; mi++)
#pragma unroll
        for (int ni = 0; ni < 4; ni++)
            wmma::load_matrix_sync(acc[mi][ni], biasf + wn * 64 + ni * 16,
                                   264, wmma::mem_row_major);
    __syncthreads();

    build_A_rep(AsBase + 0 * AS_STAGE, 0, row0, nNodes, tid);
    load_B(BsBase + 0 * BS_STAGE, 0, tid);
    CP_COMMIT();
    build_A_rep(AsBase + 1 * AS_STAGE, 1, row0, nNodes, tid);
    load_B(BsBase + 1 * BS_STAGE, 1, tid);
    CP_COMMIT();

    for (int ks = 0; ks < NKS; ks++) {
        const int cbuf = ks % STAGES;
        const __half* As = AsBase + cbuf * AS_STAGE;
        const __half* Bs = BsBase + cbuf * BS_STAGE;

        if (ks < NKS - 1) { CP_WAIT(1); } else { CP_WAIT(0); }
        __syncthreads();

        if (ks + 2 < NKS) {
            const int wbuf = (ks + 2) % STAGES;
            load_A_x(AsBase + wbuf * AS_STAGE, ks + 2, row0, nNodes, tid);
            load_B(BsBase + wbuf * BS_STAGE, ks + 2, tid);
            CP_COMMIT();
        }

#pragma unroll
        for (int k16 = 0; k16 < 2; k16++) {
            AFrag af[2];
            BFrag bf[4];
#pragma unroll
            for (int mi = 0; mi < 2; mi++)
                wmma::load_matrix_sync(af[mi],
                    As + (wm * 32 + mi * 16) * AS_LD + k16 * 16, AS_LD);
#pragma unroll
            for (int ni = 0; ni < 4; ni++)
                wmma::load_matrix_sync(bf[ni],
                    Bs + (k16 * 16) * BS_LD + wn * 64 + ni * 16, BS_LD);
#pragma unroll
            for (int mi = 0; mi < 2; mi++)
#pragma unroll
                for (int ni = 0; ni < 4; ni++)
                    wmma::mma_sync(acc[mi][ni], af[mi], bf[ni], acc[mi][ni]);
        }
    }

#pragma unroll
    for (int mi = 0; mi < 2; mi++)
#pragma unroll
        for (int ni = 0; ni < 4; ni++)
#pragma unroll
            for (int t = 0; t < acc[mi][ni].num_elements; t++)
                acc[mi][ni].x[t] = fmaxf(acc[mi][ni].x[t], 0.f);

    __syncthreads();

    if (row0 + 64 <= nNodes) {
#pragma unroll
        for (int mi = 0; mi < 2; mi++)
#pragma unroll
            for (int ni = 0; ni < 4; ni++)
                wmma::store_matrix_sync(
                    out + (size_t)(row0 + wm * 32 + mi * 16) * COUT
                        + wn * 64 + ni * 16,
                    acc[mi][ni], COUT, wmma::mem_row_major);
    } else {
        float* stg = reinterpret_cast<float*>(smem);
        for (int chunk = 0; chunk < 2; chunk++) {
            __syncthreads();
            if (wm == chunk) {
#pragma unroll
                for (int mi = 0; mi < 2; mi++)
#pragma unroll
                    for (int ni = 0; ni < 4; ni++)
                        wmma::store_matrix_sync(
                            stg + (mi * 16) * 264 + wn * 64 + ni * 16,
                            acc[mi][ni], 264, wmma::mem_row_major);
            }
            __syncthreads();
            int base = row0 + chunk * 32;
            for (int idx = tid; idx < 32 * 256; idx += 256) {
                int r = idx >> 8, c = idx & 255;
                int gr = base + r;
                if (gr < nNodes)
                    out[(size_t)gr * COUT + c] = stg[r * 264 + c];
            }
        }
    }
}

// ---------------------------------------------------------------------------
extern "C" void kernel_launch(void* const* d_in, const int* in_sizes, int n_in,
                              void* d_out, int out_size) {
    const float*  D   = (const float*)d_in[0];
    const int*    row = (const int*)d_in[1];
    const float4* ea  = (const float4*)d_in[2];
    const float*  X   = (const float*)d_in[3];
    const float*  Wp  = (const float*)d_in[4];
    const float*  bp  = (const float*)d_in[5];
    const float*  Ws  = (const float*)d_in[6];
    const float*  bs  = (const float*)d_in[7];
    float* out = (float*)d_out;

    const int nNodes = in_sizes[0];
    const int E      = in_sizes[1];

    static bool attr_set = false;
    if (!attr_set) {
        cudaFuncSetAttribute(gemm_kernel,
                             cudaFuncAttributeMaxDynamicSharedMemorySize,
                             SMEM_BYTES);
        attr_set = true;
    }

    {   // fused vectorized init
        init_kernel<<<(N_INIT + 255) / 256, 256>>>(D, X, Wp, Ws);
    }
    {   // scatter
        int total8 = E * 8;
        scatter_kernel<<<(total8 + 255) / 256, 256>>>(ea, row, total8);
    }
    {   // fp16 GEMM
        int grid = (nNodes + 63) / 64;
        gemm_kernel<<<grid, 256, SMEM_BYTES>>>(bp, bs, out, nNodes);
    }
}